// round 1
// baseline (speedup 1.0000x reference)
#include <cuda_runtime.h>
#include <cuda_bf16.h>

#define D    128
#define NGc  10000
#define NUc  100000
#define NIc  20000
#define EGIc 400000
#define EGUc 400000

// ---------------- scratch (device globals; no allocation allowed) -------------
__device__ float4 g_acc_i[NGc * 32];    // layer1 item->group sum
__device__ float4 g_acc_u[NGc * 32];    // layer1 user->group sum
__device__ float4 g_acc2_i[NGc * 32];   // layer2 item->group sum
__device__ float4 g_acc2_u[NGc * 32];   // layer2 user->group sum
__device__ int    g_cnt_i[NGc];
__device__ int    g_cnt_u[NGc];
__device__ float  g_g1[NGc * D];
__device__ float  g_i1[NIc * D];
__device__ float  g_u1[NUc * D];
__device__ float  g_g2[NGc * D];

// ---------------- scatter-sum: one warp per edge, float4 RED ------------------
__global__ void scatter_kernel(const int* __restrict__ grp, const int* __restrict__ nbr,
                               const float4* __restrict__ feat, float4* __restrict__ acc,
                               int* cnt, int E)
{
    int gw = (blockIdx.x * blockDim.x + threadIdx.x) >> 5;
    if (gw >= E) return;
    int lane = threadIdx.x & 31;
    int g = __ldg(grp + gw);
    int n = __ldg(nbr + gw);
    float4 v = __ldg(feat + (size_t)n * 32 + lane);
    atomicAdd(acc + (size_t)g * 32 + lane, v);   // 128-bit vector RED (sm_90+)
    if (cnt && lane == 0) atomicAdd(cnt + g, 1);
}

// ---------------- out = relu(x @ W + b), x: [M,128], W: [128,128] --------------
template <int R>
__global__ void lin_relu_kernel(const float* __restrict__ x, const float* __restrict__ W,
                                const float* __restrict__ b, float* __restrict__ out, int M)
{
    __shared__ float4 xs[R][32];
    int col = threadIdx.x;
    int r0 = blockIdx.x * R;
#pragma unroll
    for (int r = 0; r < R; r++) {
        int row = r0 + r;
        ((float*)xs[r])[col] = (row < M) ? x[(size_t)row * D + col] : 0.f;
    }
    __syncthreads();
    float acc[R];
#pragma unroll
    for (int r = 0; r < R; r++) acc[r] = 0.f;
#pragma unroll 4
    for (int kq = 0; kq < 32; kq++) {
        float w0 = W[(4 * kq + 0) * D + col];
        float w1 = W[(4 * kq + 1) * D + col];
        float w2 = W[(4 * kq + 2) * D + col];
        float w3 = W[(4 * kq + 3) * D + col];
#pragma unroll
        for (int r = 0; r < R; r++) {
            float4 xv = xs[r][kq];
            acc[r] += xv.x * w0 + xv.y * w1 + xv.z * w2 + xv.w * w3;
        }
    }
    float bb = b[col];
#pragma unroll
    for (int r = 0; r < R; r++) {
        int row = r0 + r;
        if (row < M) out[(size_t)row * D + col] = fmaxf(acc[r] + bb, 0.f);
    }
}

// ------- g1 = relu( (acc_i/cnt_i) @ Wi + (acc_u/cnt_u) @ Wu + bi + bu ) --------
template <int R>
__global__ void g1_kernel(const float* __restrict__ acc_i, const float* __restrict__ acc_u,
                          const int* __restrict__ cnt_i, const int* __restrict__ cnt_u,
                          const float* __restrict__ Wi, const float* __restrict__ Wu,
                          const float* __restrict__ bi, const float* __restrict__ bu,
                          float* __restrict__ out, int M)
{
    __shared__ float4 si[R][32];
    __shared__ float4 su[R][32];
    int col = threadIdx.x;
    int r0 = blockIdx.x * R;
#pragma unroll
    for (int r = 0; r < R; r++) {
        int row = r0 + r;
        int rr = row < M ? row : M - 1;
        float invi = 1.f / (float)max(cnt_i[rr], 1);
        float invu = 1.f / (float)max(cnt_u[rr], 1);
        ((float*)si[r])[col] = acc_i[(size_t)rr * D + col] * invi;
        ((float*)su[r])[col] = acc_u[(size_t)rr * D + col] * invu;
    }
    __syncthreads();
    float acc[R];
#pragma unroll
    for (int r = 0; r < R; r++) acc[r] = 0.f;
#pragma unroll 4
    for (int kq = 0; kq < 32; kq++) {
        float wi0 = Wi[(4 * kq + 0) * D + col], wi1 = Wi[(4 * kq + 1) * D + col];
        float wi2 = Wi[(4 * kq + 2) * D + col], wi3 = Wi[(4 * kq + 3) * D + col];
        float wu0 = Wu[(4 * kq + 0) * D + col], wu1 = Wu[(4 * kq + 1) * D + col];
        float wu2 = Wu[(4 * kq + 2) * D + col], wu3 = Wu[(4 * kq + 3) * D + col];
#pragma unroll
        for (int r = 0; r < R; r++) {
            float4 a = si[r][kq], u = su[r][kq];
            acc[r] += a.x * wi0 + a.y * wi1 + a.z * wi2 + a.w * wi3
                    + u.x * wu0 + u.y * wu1 + u.z * wu2 + u.w * wu3;
        }
    }
    float bb = bi[col] + bu[col];
#pragma unroll
    for (int r = 0; r < R; r++) {
        int row = r0 + r;
        if (row < M) out[(size_t)row * D + col] = fmaxf(acc[r] + bb, 0.f);
    }
}

// g2 = relu( (acc2_i/cnt) @ Wi + (acc2_u/cnt) @ Wu + g1 @ (Wg1+Wg2) + bi + bu )
template <int R>
__global__ void g2_kernel(const float* __restrict__ acc_i, const float* __restrict__ acc_u,
                          const float* __restrict__ g1,
                          const int* __restrict__ cnt_i, const int* __restrict__ cnt_u,
                          const float* __restrict__ Wi, const float* __restrict__ Wu,
                          const float* __restrict__ Wg1, const float* __restrict__ Wg2,
                          const float* __restrict__ bi, const float* __restrict__ bu,
                          float* __restrict__ out, int M)
{
    __shared__ float4 si[R][32];
    __shared__ float4 su[R][32];
    __shared__ float4 sg[R][32];
    int col = threadIdx.x;
    int r0 = blockIdx.x * R;
#pragma unroll
    for (int r = 0; r < R; r++) {
        int row = r0 + r;
        int rr = row < M ? row : M - 1;
        float invi = 1.f / (float)max(cnt_i[rr], 1);
        float invu = 1.f / (float)max(cnt_u[rr], 1);
        ((float*)si[r])[col] = acc_i[(size_t)rr * D + col] * invi;
        ((float*)su[r])[col] = acc_u[(size_t)rr * D + col] * invu;
        ((float*)sg[r])[col] = g1[(size_t)rr * D + col];
    }
    __syncthreads();
    float acc[R];
#pragma unroll
    for (int r = 0; r < R; r++) acc[r] = 0.f;
#pragma unroll 2
    for (int kq = 0; kq < 32; kq++) {
        float wi0 = Wi[(4 * kq + 0) * D + col], wi1 = Wi[(4 * kq + 1) * D + col];
        float wi2 = Wi[(4 * kq + 2) * D + col], wi3 = Wi[(4 * kq + 3) * D + col];
        float wu0 = Wu[(4 * kq + 0) * D + col], wu1 = Wu[(4 * kq + 1) * D + col];
        float wu2 = Wu[(4 * kq + 2) * D + col], wu3 = Wu[(4 * kq + 3) * D + col];
        float wg0 = Wg1[(4 * kq + 0) * D + col] + Wg2[(4 * kq + 0) * D + col];
        float wg1 = Wg1[(4 * kq + 1) * D + col] + Wg2[(4 * kq + 1) * D + col];
        float wg2 = Wg1[(4 * kq + 2) * D + col] + Wg2[(4 * kq + 2) * D + col];
        float wg3 = Wg1[(4 * kq + 3) * D + col] + Wg2[(4 * kq + 3) * D + col];
#pragma unroll
        for (int r = 0; r < R; r++) {
            float4 a = si[r][kq], u = su[r][kq], g = sg[r][kq];
            acc[r] += a.x * wi0 + a.y * wi1 + a.z * wi2 + a.w * wi3
                    + u.x * wu0 + u.y * wu1 + u.z * wu2 + u.w * wu3
                    + g.x * wg0 + g.y * wg1 + g.z * wg2 + g.w * wg3;
        }
    }
    float bb = bi[col] + bu[col];
#pragma unroll
    for (int r = 0; r < R; r++) {
        int row = r0 + r;
        if (row < M) out[(size_t)row * D + col] = fmaxf(acc[r] + bb, 0.f);
    }
}

// ---------------- final GEMM: C[M,N] = A[M,128] @ B[128,N] + bias --------------
#define KC 32
__global__ void __launch_bounds__(256)
gemm_final(const float* __restrict__ A, const float* __restrict__ B,
           const float* __restrict__ bias, float* __restrict__ C, int M, int N)
{
    __shared__ float As[KC][132];   // transposed A tile, padded
    __shared__ float Bs[KC][128];
    int tid = threadIdx.x;
    int tx = tid & 15, ty = tid >> 4;
    int m0 = blockIdx.y * 128, n0 = blockIdx.x * 128;

    float acc[8][8];
#pragma unroll
    for (int i = 0; i < 8; i++)
#pragma unroll
        for (int j = 0; j < 8; j++) acc[i][j] = 0.f;

    for (int k0 = 0; k0 < 128; k0 += KC) {
#pragma unroll
        for (int i = 0; i < 4; i++) {
            int q = tid + i * 256;          // 1024 float4 loads of A
            int m = q >> 3;                 // 0..127
            int kq = q & 7;                 // 0..7
            float4 v = make_float4(0.f, 0.f, 0.f, 0.f);
            int gm = m0 + m;
            if (gm < M) v = *(const float4*)(A + (size_t)gm * 128 + k0 + kq * 4);
            As[kq * 4 + 0][m] = v.x;
            As[kq * 4 + 1][m] = v.y;
            As[kq * 4 + 2][m] = v.z;
            As[kq * 4 + 3][m] = v.w;
        }
#pragma unroll
        for (int i = 0; i < 4; i++) {
            int q = tid + i * 256;
            int k = q >> 5;                 // 0..31
            int nq = q & 31;                // 0..31
            float4 v = make_float4(0.f, 0.f, 0.f, 0.f);
            int gn = n0 + nq * 4;
            if (gn < N) v = *(const float4*)(B + (size_t)(k0 + k) * N + gn);
            *(float4*)&Bs[k][nq * 4] = v;
        }
        __syncthreads();
#pragma unroll
        for (int k = 0; k < KC; k++) {
            float a[8], b[8];
            *(float4*)&a[0] = *(const float4*)&As[k][ty * 4];
            *(float4*)&a[4] = *(const float4*)&As[k][64 + ty * 4];
            *(float4*)&b[0] = *(const float4*)&Bs[k][tx * 4];
            *(float4*)&b[4] = *(const float4*)&Bs[k][64 + tx * 4];
#pragma unroll
            for (int i = 0; i < 8; i++)
#pragma unroll
                for (int j = 0; j < 8; j++) acc[i][j] += a[i] * b[j];
        }
        __syncthreads();
    }

#pragma unroll
    for (int i = 0; i < 8; i++) {
        int m = m0 + ((i < 4) ? (ty * 4 + i) : (64 + ty * 4 + (i - 4)));
        if (m >= M) continue;
#pragma unroll
        for (int jh = 0; jh < 2; jh++) {
            int n = n0 + jh * 64 + tx * 4;
            if (n < N) {
                float4 o;
                o.x = acc[i][jh * 4 + 0] + bias[n + 0];
                o.y = acc[i][jh * 4 + 1] + bias[n + 1];
                o.z = acc[i][jh * 4 + 2] + bias[n + 2];
                o.w = acc[i][jh * 4 + 3] + bias[n + 3];
                *(float4*)(C + (size_t)m * N + n) = o;
            }
        }
    }
}

// ------------------------------ launcher ---------------------------------------
extern "C" void kernel_launch(void* const* d_in, const int* in_sizes, int n_in,
                              void* d_out, int out_size)
{
    const int*   gi_src  = (const int*)d_in[3];
    const int*   gi_dst  = (const int*)d_in[4];
    const int*   gu_src  = (const int*)d_in[5];
    const int*   gu_dst  = (const int*)d_in[6];
    const float* emb_u   = (const float*)d_in[8];
    const float* emb_i   = (const float*)d_in[9];
    const float* Wl1     = (const float*)d_in[10];
    const float* Wr1     = (const float*)d_in[11];
    const float* b1      = (const float*)d_in[12];
    const float* Wl2     = (const float*)d_in[13];
    const float* Wr2     = (const float*)d_in[14];
    const float* b2      = (const float*)d_in[15];
    const float* Wp      = (const float*)d_in[16];
    const float* bp      = (const float*)d_in[17];
    float*       out     = (float*)d_out;

    float4 *acc_i, *acc_u, *acc2_i, *acc2_u;
    int *cnt_i, *cnt_u;
    float *g1p, *i1p, *u1p, *g2p;
    cudaGetSymbolAddress((void**)&acc_i,  g_acc_i);
    cudaGetSymbolAddress((void**)&acc_u,  g_acc_u);
    cudaGetSymbolAddress((void**)&acc2_i, g_acc2_i);
    cudaGetSymbolAddress((void**)&acc2_u, g_acc2_u);
    cudaGetSymbolAddress((void**)&cnt_i,  g_cnt_i);
    cudaGetSymbolAddress((void**)&cnt_u,  g_cnt_u);
    cudaGetSymbolAddress((void**)&g1p,    g_g1);
    cudaGetSymbolAddress((void**)&i1p,    g_i1);
    cudaGetSymbolAddress((void**)&u1p,    g_u1);
    cudaGetSymbolAddress((void**)&g2p,    g_g2);

    size_t accBytes = (size_t)NGc * D * sizeof(float);
    cudaMemsetAsync(acc_i,  0, accBytes);
    cudaMemsetAsync(acc_u,  0, accBytes);
    cudaMemsetAsync(acc2_i, 0, accBytes);
    cudaMemsetAsync(acc2_u, 0, accBytes);
    cudaMemsetAsync(cnt_i,  0, NGc * sizeof(int));
    cudaMemsetAsync(cnt_u,  0, NGc * sizeof(int));

    // layer 1 scatter (with counts)
    scatter_kernel<<<(EGIc * 32 + 255) / 256, 256>>>(gi_src, gi_dst, (const float4*)emb_i,
                                                     acc_i, cnt_i, EGIc);
    scatter_kernel<<<(EGUc * 32 + 255) / 256, 256>>>(gu_src, gu_dst, (const float4*)emb_u,
                                                     acc_u, cnt_u, EGUc);

    // g1 = relu(aggI @ Wl1[1] + aggU @ Wl1[3] + b1[1] + b1[3])
    g1_kernel<8><<<(NGc + 7) / 8, 128>>>((const float*)acc_i, (const float*)acc_u,
                                         cnt_i, cnt_u,
                                         Wl1 + 1 * D * D, Wl1 + 3 * D * D,
                                         b1 + 1 * D, b1 + 3 * D, g1p, NGc);

    // i1 = relu(emb_item @ Wr1[0] + b1[0]); u1 = relu(emb_user @ Wr1[2] + b1[2])
    lin_relu_kernel<16><<<(NIc + 15) / 16, 128>>>(emb_i, Wr1 + 0 * D * D, b1 + 0 * D, i1p, NIc);
    lin_relu_kernel<16><<<(NUc + 15) / 16, 128>>>(emb_u, Wr1 + 2 * D * D, b1 + 2 * D, u1p, NUc);

    // layer 2 scatter (counts already computed)
    scatter_kernel<<<(EGIc * 32 + 255) / 256, 256>>>(gi_src, gi_dst, (const float4*)i1p,
                                                     acc2_i, (int*)nullptr, EGIc);
    scatter_kernel<<<(EGUc * 32 + 255) / 256, 256>>>(gu_src, gu_dst, (const float4*)u1p,
                                                     acc2_u, (int*)nullptr, EGUc);

    // g2
    g2_kernel<8><<<(NGc + 7) / 8, 128>>>((const float*)acc2_i, (const float*)acc2_u, g1p,
                                         cnt_i, cnt_u,
                                         Wl2 + 1 * D * D, Wl2 + 3 * D * D,
                                         Wr2 + 1 * D * D, Wr2 + 3 * D * D,
                                         b2 + 1 * D, b2 + 3 * D, g2p, NGc);

    // out = g2 @ Wp + bp   (10000 x 20000 x 128)
    dim3 grid((NIc + 127) / 128, (NGc + 127) / 128);
    gemm_final<<<grid, 256>>>(g2p, Wp, bp, out, NGc, NIc);
}

// round 2
// speedup vs baseline: 1.1986x; 1.1986x over previous
#include <cuda_runtime.h>
#include <cuda_bf16.h>
#include <cstdint>

#define D    128
#define NGc  10000
#define NUc  100000
#define NIc  20000
#define EGIc 400000
#define EGUc 400000

// ---------------- scratch (device globals; no allocation allowed) -------------
__device__ float4 g_acc_i[NGc * 32];
__device__ float4 g_acc_u[NGc * 32];
__device__ float4 g_acc2_i[NGc * 32];
__device__ float4 g_acc2_u[NGc * 32];
__device__ int    g_cnt_i[NGc];
__device__ int    g_cnt_u[NGc];
__device__ float  g_g1[NGc * D];
__device__ float  g_i1[NIc * D];
__device__ float  g_u1[NUc * D];
__device__ __nv_bfloat16 g_Ahi[NGc * D];
__device__ __nv_bfloat16 g_Alo[NGc * D];
__device__ __nv_bfloat16 g_Bhi[NIc * D];   // WpT split: [n][k]
__device__ __nv_bfloat16 g_Blo[NIc * D];

// ---------------- scatter-sum: one warp per edge, float4 RED ------------------
__global__ void scatter_kernel(const int* __restrict__ grp, const int* __restrict__ nbr,
                               const float4* __restrict__ feat, float4* __restrict__ acc,
                               int* cnt, int E)
{
    int gw = (blockIdx.x * blockDim.x + threadIdx.x) >> 5;
    if (gw >= E) return;
    int lane = threadIdx.x & 31;
    int g = __ldg(grp + gw);
    int n = __ldg(nbr + gw);
    float4 v = __ldg(feat + (size_t)n * 32 + lane);
    atomicAdd(acc + (size_t)g * 32 + lane, v);
    if (cnt && lane == 0) atomicAdd(cnt + g, 1);
}

// ---------------- out = relu(x @ W + b), x: [M,128], W: [128,128] --------------
template <int R>
__global__ void lin_relu_kernel(const float* __restrict__ x, const float* __restrict__ W,
                                const float* __restrict__ b, float* __restrict__ out, int M)
{
    __shared__ float4 xs[R][32];
    int col = threadIdx.x;
    int r0 = blockIdx.x * R;
#pragma unroll
    for (int r = 0; r < R; r++) {
        int row = r0 + r;
        ((float*)xs[r])[col] = (row < M) ? x[(size_t)row * D + col] : 0.f;
    }
    __syncthreads();
    float acc[R];
#pragma unroll
    for (int r = 0; r < R; r++) acc[r] = 0.f;
#pragma unroll 4
    for (int kq = 0; kq < 32; kq++) {
        float w0 = W[(4 * kq + 0) * D + col];
        float w1 = W[(4 * kq + 1) * D + col];
        float w2 = W[(4 * kq + 2) * D + col];
        float w3 = W[(4 * kq + 3) * D + col];
#pragma unroll
        for (int r = 0; r < R; r++) {
            float4 xv = xs[r][kq];
            acc[r] += xv.x * w0 + xv.y * w1 + xv.z * w2 + xv.w * w3;
        }
    }
    float bb = b[col];
#pragma unroll
    for (int r = 0; r < R; r++) {
        int row = r0 + r;
        if (row < M) out[(size_t)row * D + col] = fmaxf(acc[r] + bb, 0.f);
    }
}

// ------- g1 = relu( (acc_i/cnt_i) @ Wi + (acc_u/cnt_u) @ Wu + bi + bu ) --------
template <int R>
__global__ void g1_kernel(const float* __restrict__ acc_i, const float* __restrict__ acc_u,
                          const int* __restrict__ cnt_i, const int* __restrict__ cnt_u,
                          const float* __restrict__ Wi, const float* __restrict__ Wu,
                          const float* __restrict__ bi, const float* __restrict__ bu,
                          float* __restrict__ out, int M)
{
    __shared__ float4 si[R][32];
    __shared__ float4 su[R][32];
    int col = threadIdx.x;
    int r0 = blockIdx.x * R;
#pragma unroll
    for (int r = 0; r < R; r++) {
        int row = r0 + r;
        int rr = row < M ? row : M - 1;
        float invi = 1.f / (float)max(cnt_i[rr], 1);
        float invu = 1.f / (float)max(cnt_u[rr], 1);
        ((float*)si[r])[col] = acc_i[(size_t)rr * D + col] * invi;
        ((float*)su[r])[col] = acc_u[(size_t)rr * D + col] * invu;
    }
    __syncthreads();
    float acc[R];
#pragma unroll
    for (int r = 0; r < R; r++) acc[r] = 0.f;
#pragma unroll 4
    for (int kq = 0; kq < 32; kq++) {
        float wi0 = Wi[(4 * kq + 0) * D + col], wi1 = Wi[(4 * kq + 1) * D + col];
        float wi2 = Wi[(4 * kq + 2) * D + col], wi3 = Wi[(4 * kq + 3) * D + col];
        float wu0 = Wu[(4 * kq + 0) * D + col], wu1 = Wu[(4 * kq + 1) * D + col];
        float wu2 = Wu[(4 * kq + 2) * D + col], wu3 = Wu[(4 * kq + 3) * D + col];
#pragma unroll
        for (int r = 0; r < R; r++) {
            float4 a = si[r][kq], u = su[r][kq];
            acc[r] += a.x * wi0 + a.y * wi1 + a.z * wi2 + a.w * wi3
                    + u.x * wu0 + u.y * wu1 + u.z * wu2 + u.w * wu3;
        }
    }
    float bb = bi[col] + bu[col];
#pragma unroll
    for (int r = 0; r < R; r++) {
        int row = r0 + r;
        if (row < M) out[(size_t)row * D + col] = fmaxf(acc[r] + bb, 0.f);
    }
}

// g2 = relu(...) -> emitted directly as bf16 hi/lo split for the tensor GEMM
template <int R>
__global__ void g2_kernel(const float* __restrict__ acc_i, const float* __restrict__ acc_u,
                          const float* __restrict__ g1,
                          const int* __restrict__ cnt_i, const int* __restrict__ cnt_u,
                          const float* __restrict__ Wi, const float* __restrict__ Wu,
                          const float* __restrict__ Wg1, const float* __restrict__ Wg2,
                          const float* __restrict__ bi, const float* __restrict__ bu,
                          __nv_bfloat16* __restrict__ ahi, __nv_bfloat16* __restrict__ alo,
                          int M)
{
    __shared__ float4 si[R][32];
    __shared__ float4 su[R][32];
    __shared__ float4 sg[R][32];
    int col = threadIdx.x;
    int r0 = blockIdx.x * R;
#pragma unroll
    for (int r = 0; r < R; r++) {
        int row = r0 + r;
        int rr = row < M ? row : M - 1;
        float invi = 1.f / (float)max(cnt_i[rr], 1);
        float invu = 1.f / (float)max(cnt_u[rr], 1);
        ((float*)si[r])[col] = acc_i[(size_t)rr * D + col] * invi;
        ((float*)su[r])[col] = acc_u[(size_t)rr * D + col] * invu;
        ((float*)sg[r])[col] = g1[(size_t)rr * D + col];
    }
    __syncthreads();
    float acc[R];
#pragma unroll
    for (int r = 0; r < R; r++) acc[r] = 0.f;
#pragma unroll 2
    for (int kq = 0; kq < 32; kq++) {
        float wi0 = Wi[(4 * kq + 0) * D + col], wi1 = Wi[(4 * kq + 1) * D + col];
        float wi2 = Wi[(4 * kq + 2) * D + col], wi3 = Wi[(4 * kq + 3) * D + col];
        float wu0 = Wu[(4 * kq + 0) * D + col], wu1 = Wu[(4 * kq + 1) * D + col];
        float wu2 = Wu[(4 * kq + 2) * D + col], wu3 = Wu[(4 * kq + 3) * D + col];
        float wg0 = Wg1[(4 * kq + 0) * D + col] + Wg2[(4 * kq + 0) * D + col];
        float wg1 = Wg1[(4 * kq + 1) * D + col] + Wg2[(4 * kq + 1) * D + col];
        float wg2 = Wg1[(4 * kq + 2) * D + col] + Wg2[(4 * kq + 2) * D + col];
        float wg3 = Wg1[(4 * kq + 3) * D + col] + Wg2[(4 * kq + 3) * D + col];
#pragma unroll
        for (int r = 0; r < R; r++) {
            float4 a = si[r][kq], u = su[r][kq], g = sg[r][kq];
            acc[r] += a.x * wi0 + a.y * wi1 + a.z * wi2 + a.w * wi3
                    + u.x * wu0 + u.y * wu1 + u.z * wu2 + u.w * wu3
                    + g.x * wg0 + g.y * wg1 + g.z * wg2 + g.w * wg3;
        }
    }
    float bb = bi[col] + bu[col];
#pragma unroll
    for (int r = 0; r < R; r++) {
        int row = r0 + r;
        if (row < M) {
            float v = fmaxf(acc[r] + bb, 0.f);
            __nv_bfloat16 hi = __float2bfloat16(v);
            ahi[(size_t)row * D + col] = hi;
            alo[(size_t)row * D + col] = __float2bfloat16(v - __bfloat162float(hi));
        }
    }
}

// ------- Wp [128,20000] fp32 -> WpT [20000,128] bf16 hi/lo (tiled transpose) ----
__global__ void conv_wp_kernel(const float* __restrict__ Wp,
                               __nv_bfloat16* __restrict__ bhi,
                               __nv_bfloat16* __restrict__ blo)
{
    __shared__ float t[32][33];
    int n0 = blockIdx.x * 32, k0 = blockIdx.y * 32;
    int tx = threadIdx.x & 31, ty = threadIdx.x >> 5;
#pragma unroll
    for (int r = ty; r < 32; r += 8)
        t[r][tx] = Wp[(size_t)(k0 + r) * NIc + n0 + tx];
    __syncthreads();
#pragma unroll
    for (int r = ty; r < 32; r += 8) {
        float v = t[tx][r];                 // Wp[k0+tx][n0+r]
        int n = n0 + r, k = k0 + tx;
        __nv_bfloat16 hi = __float2bfloat16(v);
        bhi[(size_t)n * D + k] = hi;
        blo[(size_t)n * D + k] = __float2bfloat16(v - __bfloat162float(hi));
    }
}

// ---------------- tensor-core final GEMM: C = A @ B^T + bias -------------------
// A: [M,128] bf16 hi/lo (row-major k-contig), B: [N,128] bf16 hi/lo (row-major
// k-contig = WpT). C fp32 [M,N]. Split product: hh + hl + lh.
#define SMSTRIDE 136   // bf16 elems per smem row (padded: conflict-free frag LDS)

__device__ __forceinline__ void mma16816(float* c, const uint32_t* a, const uint32_t* b)
{
    asm volatile(
        "mma.sync.aligned.m16n8k16.row.col.f32.bf16.bf16.f32 "
        "{%0,%1,%2,%3}, {%4,%5,%6,%7}, {%8,%9}, {%0,%1,%2,%3};\n"
        : "+f"(c[0]), "+f"(c[1]), "+f"(c[2]), "+f"(c[3])
        : "r"(a[0]), "r"(a[1]), "r"(a[2]), "r"(a[3]), "r"(b[0]), "r"(b[1]));
}

__global__ void __launch_bounds__(256, 1)
gemm_bf16_split(const __nv_bfloat16* __restrict__ Ahi, const __nv_bfloat16* __restrict__ Alo,
                const __nv_bfloat16* __restrict__ Bhi, const __nv_bfloat16* __restrict__ Blo,
                const float* __restrict__ bias, float* __restrict__ C, int M, int N)
{
    extern __shared__ __nv_bfloat16 sm[];
    __nv_bfloat16* As_h = sm;
    __nv_bfloat16* As_l = As_h + 128 * SMSTRIDE;
    __nv_bfloat16* Bs_h = As_l + 128 * SMSTRIDE;
    __nv_bfloat16* Bs_l = Bs_h + 128 * SMSTRIDE;

    int tid = threadIdx.x;
    int m0 = blockIdx.y * 128, n0 = blockIdx.x * 128;

    // load A/B tiles (16B chunks), zero-fill out-of-range rows
    uint4 zz = make_uint4(0, 0, 0, 0);
    for (int idx = tid; idx < 2048; idx += 256) {
        int row = idx >> 4;
        int c8 = (idx & 15) << 3;               // bf16 col
        int gm = m0 + row;
        uint4 vh = zz, vl = zz;
        if (gm < M) {
            vh = *(const uint4*)(Ahi + (size_t)gm * 128 + c8);
            vl = *(const uint4*)(Alo + (size_t)gm * 128 + c8);
        }
        *(uint4*)(As_h + row * SMSTRIDE + c8) = vh;
        *(uint4*)(As_l + row * SMSTRIDE + c8) = vl;
        int gn = n0 + row;
        uint4 wh = zz, wl = zz;
        if (gn < N) {
            wh = *(const uint4*)(Bhi + (size_t)gn * 128 + c8);
            wl = *(const uint4*)(Blo + (size_t)gn * 128 + c8);
        }
        *(uint4*)(Bs_h + row * SMSTRIDE + c8) = wh;
        *(uint4*)(Bs_l + row * SMSTRIDE + c8) = wl;
    }
    __syncthreads();

    int lane = tid & 31, w = tid >> 5;
    int wm = w >> 2, wn = w & 3;               // 2 x 4 warp grid, warp tile 64x32
    int r = lane >> 2, c2 = (lane & 3) * 2;

    float acc[4][4][4];
#pragma unroll
    for (int i = 0; i < 4; i++)
#pragma unroll
        for (int j = 0; j < 4; j++)
#pragma unroll
            for (int q = 0; q < 4; q++) acc[i][j][q] = 0.f;

#pragma unroll
    for (int ks = 0; ks < 8; ks++) {
        int kb = ks * 16 + c2;
        uint32_t ah[4][4], al[4][4], bh[4][2], bl[4][2];
#pragma unroll
        for (int i = 0; i < 4; i++) {
            const __nv_bfloat16* pa = As_h + (wm * 64 + i * 16 + r) * SMSTRIDE + kb;
            ah[i][0] = *(const uint32_t*)(pa);
            ah[i][1] = *(const uint32_t*)(pa + 8 * SMSTRIDE);
            ah[i][2] = *(const uint32_t*)(pa + 8);
            ah[i][3] = *(const uint32_t*)(pa + 8 * SMSTRIDE + 8);
            const __nv_bfloat16* pl = As_l + (wm * 64 + i * 16 + r) * SMSTRIDE + kb;
            al[i][0] = *(const uint32_t*)(pl);
            al[i][1] = *(const uint32_t*)(pl + 8 * SMSTRIDE);
            al[i][2] = *(const uint32_t*)(pl + 8);
            al[i][3] = *(const uint32_t*)(pl + 8 * SMSTRIDE + 8);
        }
#pragma unroll
        for (int j = 0; j < 4; j++) {
            const __nv_bfloat16* pb = Bs_h + (wn * 32 + j * 8 + r) * SMSTRIDE + kb;
            bh[j][0] = *(const uint32_t*)(pb);
            bh[j][1] = *(const uint32_t*)(pb + 8);
            const __nv_bfloat16* ql = Bs_l + (wn * 32 + j * 8 + r) * SMSTRIDE + kb;
            bl[j][0] = *(const uint32_t*)(ql);
            bl[j][1] = *(const uint32_t*)(ql + 8);
        }
#pragma unroll
        for (int i = 0; i < 4; i++)
#pragma unroll
            for (int j = 0; j < 4; j++) {
                mma16816(acc[i][j], ah[i], bh[j]);
                mma16816(acc[i][j], ah[i], bl[j]);
                mma16816(acc[i][j], al[i], bh[j]);
            }
    }

#pragma unroll
    for (int i = 0; i < 4; i++) {
#pragma unroll
        for (int j = 0; j < 4; j++) {
            int m = m0 + wm * 64 + i * 16 + r;
            int n = n0 + wn * 32 + j * 8 + c2;
            if (n < N) {
                float bx = __ldg(bias + n), by = __ldg(bias + n + 1);
                if (m < M) {
                    float2 o = make_float2(acc[i][j][0] + bx, acc[i][j][1] + by);
                    *(float2*)(C + (size_t)m * N + n) = o;
                }
                if (m + 8 < M) {
                    float2 o = make_float2(acc[i][j][2] + bx, acc[i][j][3] + by);
                    *(float2*)(C + (size_t)(m + 8) * N + n) = o;
                }
            }
        }
    }
}

// ------------------------------ launcher ---------------------------------------
extern "C" void kernel_launch(void* const* d_in, const int* in_sizes, int n_in,
                              void* d_out, int out_size)
{
    const int*   gi_src  = (const int*)d_in[3];
    const int*   gi_dst  = (const int*)d_in[4];
    const int*   gu_src  = (const int*)d_in[5];
    const int*   gu_dst  = (const int*)d_in[6];
    const float* emb_u   = (const float*)d_in[8];
    const float* emb_i   = (const float*)d_in[9];
    const float* Wl1     = (const float*)d_in[10];
    const float* Wr1     = (const float*)d_in[11];
    const float* b1      = (const float*)d_in[12];
    const float* Wl2     = (const float*)d_in[13];
    const float* Wr2     = (const float*)d_in[14];
    const float* b2      = (const float*)d_in[15];
    const float* Wp      = (const float*)d_in[16];
    const float* bp      = (const float*)d_in[17];
    float*       out     = (float*)d_out;

    float4 *acc_i, *acc_u, *acc2_i, *acc2_u;
    int *cnt_i, *cnt_u;
    float *g1p, *i1p, *u1p;
    __nv_bfloat16 *ahi, *alo, *bhi, *blo;
    cudaGetSymbolAddress((void**)&acc_i,  g_acc_i);
    cudaGetSymbolAddress((void**)&acc_u,  g_acc_u);
    cudaGetSymbolAddress((void**)&acc2_i, g_acc2_i);
    cudaGetSymbolAddress((void**)&acc2_u, g_acc2_u);
    cudaGetSymbolAddress((void**)&cnt_i,  g_cnt_i);
    cudaGetSymbolAddress((void**)&cnt_u,  g_cnt_u);
    cudaGetSymbolAddress((void**)&g1p,    g_g1);
    cudaGetSymbolAddress((void**)&i1p,    g_i1);
    cudaGetSymbolAddress((void**)&u1p,    g_u1);
    cudaGetSymbolAddress((void**)&ahi,    g_Ahi);
    cudaGetSymbolAddress((void**)&alo,    g_Alo);
    cudaGetSymbolAddress((void**)&bhi,    g_Bhi);
    cudaGetSymbolAddress((void**)&blo,    g_Blo);

    size_t accBytes = (size_t)NGc * D * sizeof(float);
    cudaMemsetAsync(acc_i,  0, accBytes);
    cudaMemsetAsync(acc_u,  0, accBytes);
    cudaMemsetAsync(acc2_i, 0, accBytes);
    cudaMemsetAsync(acc2_u, 0, accBytes);
    cudaMemsetAsync(cnt_i,  0, NGc * sizeof(int));
    cudaMemsetAsync(cnt_u,  0, NGc * sizeof(int));

    // Wp transpose + bf16 split (independent of everything else)
    conv_wp_kernel<<<dim3(NIc / 32, D / 32), 256>>>(Wp, bhi, blo);

    // layer 1 scatter (with counts)
    scatter_kernel<<<(EGIc * 32 + 255) / 256, 256>>>(gi_src, gi_dst, (const float4*)emb_i,
                                                     acc_i, cnt_i, EGIc);
    scatter_kernel<<<(EGUc * 32 + 255) / 256, 256>>>(gu_src, gu_dst, (const float4*)emb_u,
                                                     acc_u, cnt_u, EGUc);

    g1_kernel<8><<<(NGc + 7) / 8, 128>>>((const float*)acc_i, (const float*)acc_u,
                                         cnt_i, cnt_u,
                                         Wl1 + 1 * D * D, Wl1 + 3 * D * D,
                                         b1 + 1 * D, b1 + 3 * D, g1p, NGc);

    lin_relu_kernel<32><<<(NIc + 31) / 32, 128>>>(emb_i, Wr1 + 0 * D * D, b1 + 0 * D, i1p, NIc);
    lin_relu_kernel<32><<<(NUc + 31) / 32, 128>>>(emb_u, Wr1 + 2 * D * D, b1 + 2 * D, u1p, NUc);

    scatter_kernel<<<(EGIc * 32 + 255) / 256, 256>>>(gi_src, gi_dst, (const float4*)i1p,
                                                     acc2_i, (int*)nullptr, EGIc);
    scatter_kernel<<<(EGUc * 32 + 255) / 256, 256>>>(gu_src, gu_dst, (const float4*)u1p,
                                                     acc2_u, (int*)nullptr, EGUc);

    g2_kernel<8><<<(NGc + 7) / 8, 128>>>((const float*)acc2_i, (const float*)acc2_u, g1p,
                                         cnt_i, cnt_u,
                                         Wl2 + 1 * D * D, Wl2 + 3 * D * D,
                                         Wr2 + 1 * D * D, Wr2 + 3 * D * D,
                                         b2 + 1 * D, b2 + 3 * D, ahi, alo, NGc);

    // out = g2 @ WpT^T + bp  via bf16 split tensor GEMM
    int smemBytes = 4 * 128 * SMSTRIDE * sizeof(__nv_bfloat16);
    cudaFuncSetAttribute(gemm_bf16_split, cudaFuncAttributeMaxDynamicSharedMemorySize, smemBytes);
    dim3 grid((NIc + 127) / 128, (NGc + 127) / 128);
    gemm_bf16_split<<<grid, 256, smemBytes>>>(ahi, alo, bhi, blo, bp, out, NGc, NIc);
}